// round 15
// baseline (speedup 1.0000x reference)
#include <cuda_runtime.h>
#include <cstdint>

// Problem constants (fixed shapes per reference)
#define NN 100000
#define EE 1600000
#define HID 64

// fixed-point scale 2^20; per-term bias 2^24 keeps both packed halves positive
#define FPSCALE 1048576.0f
#define FPINV   (1.0f / 1048576.0f)
#define FPBIAS  (1 << 24)

// ---------------- device scratch (no allocations allowed) ----------------
__device__ int   g_cnts[NN];       // out-degree (src) counter [reset by finish_fc]
__device__ int   g_cntd[NN];       // in-degree (dst) counter  [reset by finish_fc]
__device__ int   g_fills[NN];      // src ticket counters (zeroed by scan each call)
__device__ int   g_rps[NN + 1];    // rowptr by src
__device__ float g_dinv[NN];       // rsqrt(in-degree + 1)
__device__ int   g_dstl[EE];       // dst list grouped by src
__device__ __align__(256) float g_h1[(size_t)NN * HID];  // premultiplied transform out
__device__ __align__(256) unsigned long long g_accu[(size_t)NN * 32]; // packed accumulator
__device__ __align__(256) float g_ha[(size_t)NN * HID];  // post-layer activations

// ---------------- cp.async helpers ----------------
__device__ __forceinline__ void cp16(void* s, const void* g) {
    unsigned saddr = (unsigned)__cvta_generic_to_shared(s);
    asm volatile("cp.async.cg.shared.global [%0], [%1], 16;\n" :: "r"(saddr), "l"(g));
}
__device__ __forceinline__ void cp_commit() {
    asm volatile("cp.async.commit_group;\n");
}
template <int N>
__device__ __forceinline__ void cp_wait() {
    asm volatile("cp.async.wait_group %0;\n" :: "n"(N));
}

// per-warp edge dtype detection (int64 vs int32), no global state
__device__ __forceinline__ bool warp_is64(const void* ei) {
    int lane = threadIdx.x & 31;
    const long long* p = (const long long*)ei;
    long long v0 = p[lane * 2];
    long long v1 = p[lane * 2 + 1];
    bool ok = (v0 >= 0) && (v0 < NN) && (v1 >= 0) && (v1 < NN);
    return __all_sync(0xffffffffu, ok);
}

__device__ __forceinline__ void load_edge(const void* ei, int E, bool is64, int e,
                                          int& src, int& dst) {
    if (is64) {
        src = (int)((const long long*)ei)[e];
        dst = (int)((const long long*)ei)[E + e];
    } else {
        src = ((const int*)ei)[e];
        dst = ((const int*)ei)[E + e];
    }
}

// ---------------- 1: dual degree count ----------------
__global__ __launch_bounds__(256) void count2_kernel(const void* ei, int E) {
    bool is64 = warp_is64(ei);
    int e = blockIdx.x * blockDim.x + threadIdx.x;
    if (e >= E) return;
    int src, dst;
    load_edge(ei, E, is64, e, src, dst);
    atomicAdd(&g_cnts[src], 1);
    atomicAdd(&g_cntd[dst], 1);
}

// ---------------- 2: scan src counts -> rowptr; dinv from dst counts; zero fills ----------------
__global__ __launch_bounds__(1024) void scan_kernel(int n) {
    const int tid = threadIdx.x;
    __shared__ int wsum[32];
    __shared__ int carry;
    if (tid == 0) carry = 0;
    __syncthreads();
    const int4* c4 = (const int4*)g_cnts;
    const int4* d4 = (const int4*)g_cntd;
    int nv4 = n >> 2;
    for (int base = 0; base < nv4; base += 1024) {
        int idx = base + tid;
        int4 v = make_int4(0, 0, 0, 0);
        if (idx < nv4) v = c4[idx];
        int s = v.x + v.y + v.z + v.w;
        int x = s;
        #pragma unroll
        for (int o = 1; o < 32; o <<= 1) {
            int y = __shfl_up_sync(0xffffffffu, x, o);
            if ((tid & 31) >= o) x += y;
        }
        if ((tid & 31) == 31) wsum[tid >> 5] = x;
        __syncthreads();
        if (tid < 32) {
            int w = wsum[tid];
            #pragma unroll
            for (int o = 1; o < 32; o <<= 1) {
                int y = __shfl_up_sync(0xffffffffu, w, o);
                if (tid >= o) w += y;
            }
            wsum[tid] = w;
        }
        __syncthreads();
        int excl = x - s + ((tid >= 32) ? wsum[(tid >> 5) - 1] : 0) + carry;
        if (idx < nv4) {
            g_rps[idx * 4 + 0] = excl;
            g_rps[idx * 4 + 1] = excl + v.x;
            g_rps[idx * 4 + 2] = excl + v.x + v.y;
            g_rps[idx * 4 + 3] = excl + v.x + v.y + v.z;
            *(int4*)&g_fills[idx * 4] = make_int4(0, 0, 0, 0);
            int4 d = d4[idx];
            *(float4*)&g_dinv[idx * 4] = make_float4(
                rsqrtf((float)(d.x + 1)), rsqrtf((float)(d.y + 1)),
                rsqrtf((float)(d.z + 1)), rsqrtf((float)(d.w + 1)));
        }
        __syncthreads();
        if (tid == 1023) carry = excl + s;
        __syncthreads();
    }
    if (tid == 0) g_rps[n] = carry;
}

// ---------------- 3: group dsts by src (bucket scatter) ----------------
__global__ __launch_bounds__(256) void reorder_kernel(const void* ei, int E) {
    bool is64 = warp_is64(ei);
    int e = blockIdx.x * blockDim.x + threadIdx.x;
    if (e >= E) return;
    int src, dst;
    load_edge(ei, E, is64, e, src, dst);
    int pos = g_rps[src] + atomicAdd(&g_fills[src], 1);
    g_dstl[pos] = dst;
}

// ---------------- zero the packed accumulator (plain stores) ----------------
__global__ __launch_bounds__(256) void zero_acc_kernel() {
    int i = blockIdx.x * blockDim.x + threadIdx.x;
    if (i < NN * 16)
        *(ulonglong2*)&g_accu[(size_t)i * 2] = make_ulonglong2(0ull, 0ull);
}

// ---------------- GEMM: [M,K] @ [K,64] -> dinv[row] * result (fp32) ----------------
// Double-buffered cp.async pipeline: tile t+1's global loads overlap tile t's
// FFMA compute; no register staging of global data.
template <int K>
__global__ __launch_bounds__(256) void gemm_dinv_kernel(const float* __restrict__ A,
                                                        const float* __restrict__ B,
                                                        float* __restrict__ C, int M) {
    __shared__ float xs[2][128][32];  // [buf][row][k]
    __shared__ float ws[2][32][64];   // [buf][k][col]
    const int tid = threadIdx.x;
    const int tx = tid & 15, ty = tid >> 4;
    const int row0 = blockIdx.x * 128;
    constexpr int NT = K / 32;

    float acc[8][4] = {};

    // issue loads for a k-tile into buffer b
    auto issue_tile = [&](int t, int b) {
        const int kt = t * 32;
        #pragma unroll
        for (int it = 0; it < 4; it++) {
            int idx = tid + it * 256;
            int r = idx >> 3, c4 = idx & 7;
            int grow = min(row0 + r, M - 1);   // clamp: garbage rows discarded in epilogue
            cp16(&xs[b][r][c4 * 4], &A[(size_t)grow * K + kt + c4 * 4]);
        }
        #pragma unroll
        for (int it = 0; it < 2; it++) {
            int idx = tid + it * 256;
            int kk = idx >> 4, c4 = idx & 15;
            cp16(&ws[b][kk][c4 * 4], &B[(size_t)(kt + kk) * 64 + c4 * 4]);
        }
        cp_commit();
    };

    issue_tile(0, 0);
    int cur = 0;
    #pragma unroll
    for (int t = 0; t < NT; t++) {
        if (t + 1 < NT) {
            issue_tile(t + 1, cur ^ 1);
            cp_wait<1>();   // tile t arrived; t+1 still in flight
        } else {
            cp_wait<0>();
        }
        __syncthreads();
        #pragma unroll
        for (int k = 0; k < 32; k++) {
            float4 b = *(float4*)&ws[cur][k][tx * 4];
            #pragma unroll
            for (int r = 0; r < 8; r++) {
                float a = xs[cur][ty * 8 + r][k];
                acc[r][0] += a * b.x;
                acc[r][1] += a * b.y;
                acc[r][2] += a * b.z;
                acc[r][3] += a * b.w;
            }
        }
        __syncthreads();   // buffer consumed before it is reloaded two tiles later
        cur ^= 1;
    }
    #pragma unroll
    for (int r = 0; r < 8; r++) {
        int grow = row0 + ty * 8 + r;
        if (grow < M) {
            float di = g_dinv[grow];
            *(float4*)&C[(size_t)grow * 64 + tx * 4] =
                make_float4(di * acc[r][0], di * acc[r][1], di * acc[r][2], di * acc[r][3]);
        }
    }
}

// ---------------- push: warp per SRC node ----------------
// Row loaded + packed ONCE per src; per out-edge only shfl(dst) + RED.64.
__global__ __launch_bounds__(256) void push_kernel(int n, const float2* __restrict__ hp) {
    int i = (blockIdx.x * blockDim.x + threadIdx.x) >> 5;  // src node
    int lane = threadIdx.x & 31;
    if (i >= n) return;
    int e0 = g_rps[i];
    const int e1 = g_rps[i + 1];
    if (e0 == e1) return;
    float2 v = hp[(size_t)i * 32 + lane];
    unsigned int lo = (unsigned int)(__float2int_rn(v.x * FPSCALE) + FPBIAS);
    unsigned int hi = (unsigned int)(__float2int_rn(v.y * FPSCALE) + FPBIAS);
    unsigned long long pack = ((unsigned long long)hi << 32) | (unsigned long long)lo;

    for (int base = e0; base < e1; base += 32) {
        int idx = base + lane;
        int d = (idx < e1) ? g_dstl[idx] : 0;
        const int m = min(32, e1 - base);
        int j = 0;
        for (; j + 4 <= m; j += 4) {
            int d0 = __shfl_sync(0xffffffffu, d, j + 0);
            int d1 = __shfl_sync(0xffffffffu, d, j + 1);
            int d2 = __shfl_sync(0xffffffffu, d, j + 2);
            int d3 = __shfl_sync(0xffffffffu, d, j + 3);
            atomicAdd(&g_accu[(size_t)d0 * 32 + lane], pack);
            atomicAdd(&g_accu[(size_t)d1 * 32 + lane], pack);
            atomicAdd(&g_accu[(size_t)d2 * 32 + lane], pack);
            atomicAdd(&g_accu[(size_t)d3 * 32 + lane], pack);
        }
        for (; j < m; j++) {
            int dj = __shfl_sync(0xffffffffu, d, j);
            atomicAdd(&g_accu[(size_t)dj * 32 + lane], pack);
        }
    }
}

// unpack helper: integer bias subtraction (float would lose low bits at ~1e9)
__device__ __forceinline__ float2 unpack_acc(unsigned long long a, int deg) {
    int corr = deg * FPBIAS;
    int lo = (int)(unsigned int)(a & 0xffffffffull) - corr;
    int hi = (int)(unsigned int)(a >> 32) - corr;
    return make_float2((float)lo * FPINV, (float)hi * FPINV);
}

// ---------------- finish layer 1: ha = relu(dinv*(acc + self) + b) ----------------
__global__ __launch_bounds__(256) void finish_relu_kernel(const float2* __restrict__ hp,
                                                          const float* __restrict__ bias,
                                                          float2* __restrict__ out, int n) {
    int gid = blockIdx.x * blockDim.x + threadIdx.x;
    if (gid >= n * 32) return;
    int i = gid >> 5;
    int l = gid & 31;
    float di = g_dinv[i];
    float2 a = unpack_acc(g_accu[gid], g_cntd[i]);
    float2 s = hp[gid];
    float2 bb = ((const float2*)bias)[l];
    out[gid] = make_float2(fmaxf(di * (a.x + s.x) + bb.x, 0.f),
                           fmaxf(di * (a.y + s.y) + bb.y, 0.f));
}

// ---------------- finish layer 2 fused with final FC; resets counters ----------------
__global__ __launch_bounds__(256) void finish_fc_kernel(const float2* __restrict__ hp,
                                                        const float* __restrict__ b2,
                                                        const float* __restrict__ Wfc,
                                                        const float* __restrict__ bfc,
                                                        float* __restrict__ out, int n) {
    __shared__ float Ws[64 * 11];
    __shared__ float bs[11];
    int tid = threadIdx.x;
    for (int q = tid; q < 64 * 11; q += 256) Ws[q] = Wfc[q];
    if (tid < 11) bs[tid] = bfc[tid];
    __syncthreads();

    int wid = (blockIdx.x * blockDim.x + tid) >> 5;
    int lane = tid & 31;
    if (wid >= n) return;
    const int i = wid;
    int deg = g_cntd[i];
    if (lane == 0) { g_cnts[i] = 0; g_cntd[i] = 0; }  // reset for next call
    float di = g_dinv[i];
    float2 a = unpack_acc(g_accu[(size_t)i * 32 + lane], deg);
    float2 s = hp[(size_t)i * 32 + lane];
    float2 bb = ((const float2*)b2)[lane];
    float vx = fmaxf(di * (a.x + s.x) + bb.x, 0.f);
    float vy = fmaxf(di * (a.y + s.y) + bb.y, 0.f);

    // fused FC: lane holds features 2*lane, 2*lane+1
    #pragma unroll
    for (int j = 0; j < 11; j++) {
        float p = vx * Ws[(2 * lane) * 11 + j] + vy * Ws[(2 * lane + 1) * 11 + j];
        #pragma unroll
        for (int o = 16; o; o >>= 1) p += __shfl_xor_sync(0xffffffffu, p, o);
        if (lane == j) out[(size_t)i * 11 + j] = p + bs[j];
    }
}

// ---------------- launch ----------------
extern "C" void kernel_launch(void* const* d_in, const int* in_sizes, int n_in,
                              void* d_out, int out_size) {
    const float* x   = (const float*)d_in[0];
    const void*  ei  = d_in[1];
    const float* W1  = (const float*)d_in[2];
    const float* b1  = (const float*)d_in[3];
    const float* W2  = (const float*)d_in[4];
    const float* b2  = (const float*)d_in[5];
    const float* Wfc = (const float*)d_in[6];
    const float* bfc = (const float*)d_in[7];
    float* out = (float*)d_out;

    const int n = in_sizes[0] / 256;   // 100000
    const int E = in_sizes[1] / 2;     // 1600000

    const int TB = 256;
    int nb_edge = (E + TB - 1) / TB;                 // 6250
    int nb_gemm = (n + 127) / 128;                   // 782
    int nb_push = (n * 32 + TB - 1) / TB;            // 12500 (warp per src)
    int nb_fin  = (n * 32 + TB - 1) / TB;            // 12500
    int nb_zero = (NN * 16 + TB - 1) / TB;           // 6250

    // counters zero at first call (BSS); reset by finish_fc each call.
    count2_kernel<<<nb_edge, TB>>>(ei, E);                                  // 1
    scan_kernel<<<1, 1024>>>(n);                                            // 2
    reorder_kernel<<<nb_edge, TB>>>(ei, E);                                 // 3
    gemm_dinv_kernel<256><<<nb_gemm, TB>>>(x, W1, g_h1, n);                 // 4 <-- profiled
    zero_acc_kernel<<<nb_zero, TB>>>();                                     // 5
    push_kernel<<<nb_push, TB>>>(n, (const float2*)g_h1);                   // 6
    finish_relu_kernel<<<nb_fin, TB>>>((const float2*)g_h1, b1,
                                       (float2*)g_ha, n);                   // 7
    gemm_dinv_kernel<64><<<nb_gemm, TB>>>(g_ha, W2, g_h1, n);               // 8
    zero_acc_kernel<<<nb_zero, TB>>>();                                     // 9
    push_kernel<<<nb_push, TB>>>(n, (const float2*)g_h1);                   // 10
    finish_fc_kernel<<<nb_fin, TB>>>((const float2*)g_h1, b2,
                                     Wfc, bfc, out, n);                     // 11
}

// round 16
// speedup vs baseline: 1.0235x; 1.0235x over previous
#include <cuda_runtime.h>
#include <cstdint>

// Problem constants (fixed shapes per reference)
#define NN 100000
#define EE 1600000
#define HID 64

// fixed-point scale 2^20; per-term bias 2^24 keeps both packed halves positive
#define FPSCALE 1048576.0f
#define FPINV   (1.0f / 1048576.0f)
#define FPBIAS  (1 << 24)

// ---------------- device scratch (no allocations allowed) ----------------
__device__ int   g_cnts[NN];       // out-degree (src) counter [reset by finish_fc]
__device__ int   g_cntd[NN];       // in-degree (dst) counter  [reset by finish_fc]
__device__ int   g_fills[NN];      // src ticket counters (zeroed by scan each call)
__device__ int   g_rps[NN + 1];    // rowptr by src
__device__ float g_dinv[NN];       // rsqrt(in-degree + 1)
__device__ int   g_dstl[EE];       // dst list grouped by src
__device__ __align__(256) float g_h1[(size_t)NN * HID];  // premultiplied transform out
__device__ __align__(256) unsigned long long g_accu[(size_t)NN * 32]; // packed accumulator
__device__ __align__(256) float g_ha[(size_t)NN * HID];  // post-layer activations

// per-warp edge dtype detection (int64 vs int32), no global state
__device__ __forceinline__ bool warp_is64(const void* ei) {
    int lane = threadIdx.x & 31;
    const long long* p = (const long long*)ei;
    long long v0 = p[lane * 2];
    long long v1 = p[lane * 2 + 1];
    bool ok = (v0 >= 0) && (v0 < NN) && (v1 >= 0) && (v1 < NN);
    return __all_sync(0xffffffffu, ok);
}

__device__ __forceinline__ void load_edge(const void* ei, int E, bool is64, int e,
                                          int& src, int& dst) {
    if (is64) {
        src = (int)((const long long*)ei)[e];
        dst = (int)((const long long*)ei)[E + e];
    } else {
        src = ((const int*)ei)[e];
        dst = ((const int*)ei)[E + e];
    }
}

// ---------------- 1: dual degree count ----------------
__global__ __launch_bounds__(256) void count2_kernel(const void* ei, int E) {
    bool is64 = warp_is64(ei);
    int e = blockIdx.x * blockDim.x + threadIdx.x;
    if (e >= E) return;
    int src, dst;
    load_edge(ei, E, is64, e, src, dst);
    atomicAdd(&g_cnts[src], 1);
    atomicAdd(&g_cntd[dst], 1);
}

// ---------------- 2: scan src counts -> rowptr; dinv from dst counts; zero fills ----------------
__global__ __launch_bounds__(1024) void scan_kernel(int n) {
    const int tid = threadIdx.x;
    __shared__ int wsum[32];
    __shared__ int carry;
    if (tid == 0) carry = 0;
    __syncthreads();
    const int4* c4 = (const int4*)g_cnts;
    const int4* d4 = (const int4*)g_cntd;
    int nv4 = n >> 2;
    for (int base = 0; base < nv4; base += 1024) {
        int idx = base + tid;
        int4 v = make_int4(0, 0, 0, 0);
        if (idx < nv4) v = c4[idx];
        int s = v.x + v.y + v.z + v.w;
        int x = s;
        #pragma unroll
        for (int o = 1; o < 32; o <<= 1) {
            int y = __shfl_up_sync(0xffffffffu, x, o);
            if ((tid & 31) >= o) x += y;
        }
        if ((tid & 31) == 31) wsum[tid >> 5] = x;
        __syncthreads();
        if (tid < 32) {
            int w = wsum[tid];
            #pragma unroll
            for (int o = 1; o < 32; o <<= 1) {
                int y = __shfl_up_sync(0xffffffffu, w, o);
                if (tid >= o) w += y;
            }
            wsum[tid] = w;
        }
        __syncthreads();
        int excl = x - s + ((tid >= 32) ? wsum[(tid >> 5) - 1] : 0) + carry;
        if (idx < nv4) {
            g_rps[idx * 4 + 0] = excl;
            g_rps[idx * 4 + 1] = excl + v.x;
            g_rps[idx * 4 + 2] = excl + v.x + v.y;
            g_rps[idx * 4 + 3] = excl + v.x + v.y + v.z;
            *(int4*)&g_fills[idx * 4] = make_int4(0, 0, 0, 0);
            int4 d = d4[idx];
            *(float4*)&g_dinv[idx * 4] = make_float4(
                rsqrtf((float)(d.x + 1)), rsqrtf((float)(d.y + 1)),
                rsqrtf((float)(d.z + 1)), rsqrtf((float)(d.w + 1)));
        }
        __syncthreads();
        if (tid == 1023) carry = excl + s;
        __syncthreads();
    }
    if (tid == 0) g_rps[n] = carry;
}

// ---------------- 3: group dsts by src (bucket scatter) ----------------
__global__ __launch_bounds__(256) void reorder_kernel(const void* ei, int E) {
    bool is64 = warp_is64(ei);
    int e = blockIdx.x * blockDim.x + threadIdx.x;
    if (e >= E) return;
    int src, dst;
    load_edge(ei, E, is64, e, src, dst);
    int pos = g_rps[src] + atomicAdd(&g_fills[src], 1);
    g_dstl[pos] = dst;
}

// ---------------- zero the packed accumulator (plain stores) ----------------
__global__ __launch_bounds__(256) void zero_acc_kernel() {
    int i = blockIdx.x * blockDim.x + threadIdx.x;
    if (i < NN * 16)
        *(ulonglong2*)&g_accu[(size_t)i * 2] = make_ulonglong2(0ull, 0ull);
}

// ---------------- GEMM: [M,K] @ [K,64] -> dinv[row] * result (fp32) ----------------
// A-tile stored TRANSPOSED in smem (xs[k][row], stride 132): inner loop reads
// a-values for 8 contiguous rows with 2 LDS.128 (broadcast) instead of 8
// conflicted scalar LDS. Inner loop = 3 LDS.128 + 32 FFMA per k.
template <int K>
__global__ __launch_bounds__(256) void gemm_dinv_kernel(const float* __restrict__ A,
                                                        const float* __restrict__ B,
                                                        float* __restrict__ C, int M) {
    __shared__ float xs[32][132];  // [k][row], padded stride (132*4 % 16 == 0)
    __shared__ float ws[32][64];   // [k][col]
    const int tid = threadIdx.x;
    const int tx = tid & 15, ty = tid >> 4;
    const int row0 = blockIdx.x * 128;

    float acc[8][4] = {};

    for (int kt = 0; kt < K; kt += 32) {
        #pragma unroll
        for (int it = 0; it < 4; it++) {
            int idx = tid + it * 256;
            int r = idx >> 3, c4 = idx & 7;
            int grow = row0 + r;
            float4 v = make_float4(0.f, 0.f, 0.f, 0.f);
            if (grow < M) v = *(const float4*)&A[(size_t)grow * K + kt + c4 * 4];
            xs[c4 * 4 + 0][r] = v.x;
            xs[c4 * 4 + 1][r] = v.y;
            xs[c4 * 4 + 2][r] = v.z;
            xs[c4 * 4 + 3][r] = v.w;
        }
        #pragma unroll
        for (int it = 0; it < 2; it++) {
            int idx = tid + it * 256;
            int kk = idx >> 4, c4 = idx & 15;
            *(float4*)&ws[kk][c4 * 4] = *(const float4*)&B[(size_t)(kt + kk) * 64 + c4 * 4];
        }
        __syncthreads();
        #pragma unroll
        for (int k = 0; k < 32; k++) {
            float4 b = *(float4*)&ws[k][tx * 4];
            float4 alo = *(float4*)&xs[k][ty * 8];
            float4 ahi = *(float4*)&xs[k][ty * 8 + 4];
            float av[8] = {alo.x, alo.y, alo.z, alo.w, ahi.x, ahi.y, ahi.z, ahi.w};
            #pragma unroll
            for (int r = 0; r < 8; r++) {
                acc[r][0] += av[r] * b.x;
                acc[r][1] += av[r] * b.y;
                acc[r][2] += av[r] * b.z;
                acc[r][3] += av[r] * b.w;
            }
        }
        __syncthreads();
    }
    #pragma unroll
    for (int r = 0; r < 8; r++) {
        int grow = row0 + ty * 8 + r;
        if (grow < M) {
            float di = g_dinv[grow];
            *(float4*)&C[(size_t)grow * 64 + tx * 4] =
                make_float4(di * acc[r][0], di * acc[r][1], di * acc[r][2], di * acc[r][3]);
        }
    }
}

// ---------------- push: warp per SRC node ----------------
// Row loaded + packed ONCE per src; per out-edge only shfl(dst) + RED.64.
__global__ __launch_bounds__(256) void push_kernel(int n, const float2* __restrict__ hp) {
    int i = (blockIdx.x * blockDim.x + threadIdx.x) >> 5;  // src node
    int lane = threadIdx.x & 31;
    if (i >= n) return;
    int e0 = g_rps[i];
    const int e1 = g_rps[i + 1];
    if (e0 == e1) return;
    float2 v = hp[(size_t)i * 32 + lane];
    unsigned int lo = (unsigned int)(__float2int_rn(v.x * FPSCALE) + FPBIAS);
    unsigned int hi = (unsigned int)(__float2int_rn(v.y * FPSCALE) + FPBIAS);
    unsigned long long pack = ((unsigned long long)hi << 32) | (unsigned long long)lo;

    for (int base = e0; base < e1; base += 32) {
        int idx = base + lane;
        int d = (idx < e1) ? g_dstl[idx] : 0;
        const int m = min(32, e1 - base);
        int j = 0;
        for (; j + 4 <= m; j += 4) {
            int d0 = __shfl_sync(0xffffffffu, d, j + 0);
            int d1 = __shfl_sync(0xffffffffu, d, j + 1);
            int d2 = __shfl_sync(0xffffffffu, d, j + 2);
            int d3 = __shfl_sync(0xffffffffu, d, j + 3);
            atomicAdd(&g_accu[(size_t)d0 * 32 + lane], pack);
            atomicAdd(&g_accu[(size_t)d1 * 32 + lane], pack);
            atomicAdd(&g_accu[(size_t)d2 * 32 + lane], pack);
            atomicAdd(&g_accu[(size_t)d3 * 32 + lane], pack);
        }
        for (; j < m; j++) {
            int dj = __shfl_sync(0xffffffffu, d, j);
            atomicAdd(&g_accu[(size_t)dj * 32 + lane], pack);
        }
    }
}

// unpack helper: integer bias subtraction (float would lose low bits at ~1e9)
__device__ __forceinline__ float2 unpack_acc(unsigned long long a, int deg) {
    int corr = deg * FPBIAS;
    int lo = (int)(unsigned int)(a & 0xffffffffull) - corr;
    int hi = (int)(unsigned int)(a >> 32) - corr;
    return make_float2((float)lo * FPINV, (float)hi * FPINV);
}

// ---------------- finish layer 1: ha = relu(dinv*(acc + self) + b) ----------------
__global__ __launch_bounds__(256) void finish_relu_kernel(const float2* __restrict__ hp,
                                                          const float* __restrict__ bias,
                                                          float2* __restrict__ out, int n) {
    int gid = blockIdx.x * blockDim.x + threadIdx.x;
    if (gid >= n * 32) return;
    int i = gid >> 5;
    int l = gid & 31;
    float di = g_dinv[i];
    float2 a = unpack_acc(g_accu[gid], g_cntd[i]);
    float2 s = hp[gid];
    float2 bb = ((const float2*)bias)[l];
    out[gid] = make_float2(fmaxf(di * (a.x + s.x) + bb.x, 0.f),
                           fmaxf(di * (a.y + s.y) + bb.y, 0.f));
}

// ---------------- finish layer 2 fused with final FC; resets counters ----------------
__global__ __launch_bounds__(256) void finish_fc_kernel(const float2* __restrict__ hp,
                                                        const float* __restrict__ b2,
                                                        const float* __restrict__ Wfc,
                                                        const float* __restrict__ bfc,
                                                        float* __restrict__ out, int n) {
    __shared__ float Ws[64 * 11];
    __shared__ float bs[11];
    int tid = threadIdx.x;
    for (int q = tid; q < 64 * 11; q += 256) Ws[q] = Wfc[q];
    if (tid < 11) bs[tid] = bfc[tid];
    __syncthreads();

    int wid = (blockIdx.x * blockDim.x + tid) >> 5;
    int lane = tid & 31;
    if (wid >= n) return;
    const int i = wid;
    int deg = g_cntd[i];
    if (lane == 0) { g_cnts[i] = 0; g_cntd[i] = 0; }  // reset for next call
    float di = g_dinv[i];
    float2 a = unpack_acc(g_accu[(size_t)i * 32 + lane], deg);
    float2 s = hp[(size_t)i * 32 + lane];
    float2 bb = ((const float2*)b2)[lane];
    float vx = fmaxf(di * (a.x + s.x) + bb.x, 0.f);
    float vy = fmaxf(di * (a.y + s.y) + bb.y, 0.f);

    // fused FC: lane holds features 2*lane, 2*lane+1
    #pragma unroll
    for (int j = 0; j < 11; j++) {
        float p = vx * Ws[(2 * lane) * 11 + j] + vy * Ws[(2 * lane + 1) * 11 + j];
        #pragma unroll
        for (int o = 16; o; o >>= 1) p += __shfl_xor_sync(0xffffffffu, p, o);
        if (lane == j) out[(size_t)i * 11 + j] = p + bs[j];
    }
}

// ---------------- launch ----------------
extern "C" void kernel_launch(void* const* d_in, const int* in_sizes, int n_in,
                              void* d_out, int out_size) {
    const float* x   = (const float*)d_in[0];
    const void*  ei  = d_in[1];
    const float* W1  = (const float*)d_in[2];
    const float* b1  = (const float*)d_in[3];
    const float* W2  = (const float*)d_in[4];
    const float* b2  = (const float*)d_in[5];
    const float* Wfc = (const float*)d_in[6];
    const float* bfc = (const float*)d_in[7];
    float* out = (float*)d_out;

    const int n = in_sizes[0] / 256;   // 100000
    const int E = in_sizes[1] / 2;     // 1600000

    const int TB = 256;
    int nb_edge = (E + TB - 1) / TB;                 // 6250
    int nb_gemm = (n + 127) / 128;                   // 782
    int nb_push = (n * 32 + TB - 1) / TB;            // 12500 (warp per src)
    int nb_fin  = (n * 32 + TB - 1) / TB;            // 12500
    int nb_zero = (NN * 16 + TB - 1) / TB;           // 6250

    // counters zero at first call (BSS); reset by finish_fc each call.
    count2_kernel<<<nb_edge, TB>>>(ei, E);                                  // 1
    scan_kernel<<<1, 1024>>>(n);                                            // 2
    reorder_kernel<<<nb_edge, TB>>>(ei, E);                                 // 3
    gemm_dinv_kernel<256><<<nb_gemm, TB>>>(x, W1, g_h1, n);                 // 4 <-- profiled
    zero_acc_kernel<<<nb_zero, TB>>>();                                     // 5
    push_kernel<<<nb_push, TB>>>(n, (const float2*)g_h1);                   // 6
    finish_relu_kernel<<<nb_fin, TB>>>((const float2*)g_h1, b1,
                                       (float2*)g_ha, n);                   // 7
    gemm_dinv_kernel<64><<<nb_gemm, TB>>>(g_ha, W2, g_h1, n);               // 8
    zero_acc_kernel<<<nb_zero, TB>>>();                                     // 9
    push_kernel<<<nb_push, TB>>>(n, (const float2*)g_h1);                   // 10
    finish_fc_kernel<<<nb_fin, TB>>>((const float2*)g_h1, b2,
                                     Wfc, bfc, out, n);                     // 11
}